// round 9
// baseline (speedup 1.0000x reference)
#include <cuda_runtime.h>
#include <math.h>

#define BSZ   1024
#define NB    30
#define KNN   10
#define HID   128
#define EMB   64
#define NROWS (BSZ*NB)
#define P     34
#define RMSG  64          // rows per k_msg block
#define PK    132         // s_m pitch (A operand / y) : bank-conflict-free A frags
#define PB    136         // s_B pitch : bank-conflict-free B frags

typedef unsigned long long u64;

__device__ __forceinline__ float tanha(float x) {
    float y; asm("tanh.approx.f32 %0, %1;" : "=f"(y) : "f"(x)); return y;
}
// div-free rational tanh on the fma/alu pipes (no MUFU).
// Pade from CF depth 5: x(x^4+105x^2+945)/(15x^4+420x^2+945), clamp to [-1,1].
// err: 4e-6 @|x|=1, 1e-4 @|x|=2, <=1e-3 only for |x|>3.4 (rare), exact->1 beyond.
__device__ __forceinline__ float ptanh(float x) {
    float t = x * x;
    float n = fmaf(t + 105.0f, t, 945.0f);
    float d = fmaf(fmaf(15.0f, t, 420.0f), t, 945.0f);
    float nx = x * n;
    float r = __int_as_float(0x7EF311C3 - __float_as_int(d));
    r = r * fmaf(-d, r, 2.0f);
    r = r * fmaf(-d, r, 2.0f);
    float y = nx * r;
    return fminf(1.0f, fmaxf(-1.0f, y));
}
__device__ __forceinline__ u64 pk(float x) {
    u64 d; asm("mov.b64 %0,{%1,%1};" : "=l"(d) : "f"(x)); return d;
}
__device__ __forceinline__ u64 fma2(u64 a, u64 b, u64 c) {
    u64 d; asm("fma.rn.f32x2 %0,%1,%2,%3;" : "=l"(d) : "l"(a), "l"(b), "l"(c)); return d;
}
__device__ __forceinline__ float2 up(u64 a) {
    float2 r; asm("mov.b64 {%0,%1},%2;" : "=f"(r.x), "=f"(r.y) : "l"(a)); return r;
}
__device__ __forceinline__ unsigned tf32r(float x) {
    unsigned r; asm("cvt.rna.tf32.f32 %0, %1;" : "=r"(r) : "f"(x)); return r;
}

#define MMA_TF32(d0,d1,d2,d3,a0,a1,a2,a3,b0,b1) \
    asm volatile("mma.sync.aligned.m16n8k8.row.col.f32.tf32.tf32.f32 " \
        "{%0,%1,%2,%3},{%4,%5,%6,%7},{%8,%9},{%0,%1,%2,%3};" \
        : "+f"(d0),"+f"(d1),"+f"(d2),"+f"(d3) \
        : "r"(a0),"r"(a1),"r"(a2),"r"(a3),"r"(b0),"r"(b1))

// ---------------- device scratch ----------------
__device__ float g_cf[NB*EMB];
__device__ float g_Wcomb[192*256];
__device__ int   g_nbr[NROWS*KNN];
__device__ float g_A[NROWS*HID];
__device__ float g_C[NROWS*HID];

// ---------------- kernel 0: tiny precompute ----------------
__global__ void k_setup(const float* __restrict__ emb_tab,
                        const float* __restrict__ W_emb,
                        const float* __restrict__ b_emb,
                        const float* __restrict__ W_m1)
{
    int tid = blockIdx.x * blockDim.x + threadIdx.x;
    int stride = gridDim.x * blockDim.x;
    for (int idx = tid; idx < NB*EMB; idx += stride) {
        int n = idx / EMB, e = idx - n*EMB;
        int cat = n / (NB/3);
        float s = b_emb[e];
        for (int k = 0; k < EMB; k++)
            s += tanhf(emb_tab[cat*EMB + k]) * W_emb[k*EMB + e];
        g_cf[idx] = tanhf(s);
    }
    for (int idx = tid; idx < 192*256; idx += stride) {
        int k = idx >> 8, c = idx & 255;
        float v;
        if (c < 128) v = W_m1[k*128 + c] - W_m1[(192+k)*128 + c];
        else         v = W_m1[(192+k)*128 + (c-128)];
        g_Wcomb[idx] = v;
    }
}

// ---------------- kernel 1: per-batch KNN ----------------
__global__ void k_knn(const float* __restrict__ state_inp)
{
    __shared__ float px[NB], py[NB];
    int b = blockIdx.x, t = threadIdx.x;
    if (t < NB) { px[t] = state_inp[b*60 + 2*t]; py[t] = state_inp[b*60 + 2*t + 1]; }
    __syncthreads();
    if (t < NB) {
        float bd[KNN]; int bi[KNN];
        #pragma unroll
        for (int k = 0; k < KNN; k++) { bd[k] = 1e30f; bi[k] = 0; }
        float xi = px[t], yi = py[t];
        for (int j = 0; j < NB; j++) {
            if (j == t) continue;
            float dx = px[j] - xi, dy = py[j] - yi;
            float cd = dx*dx + dy*dy;
            int ci = j;
            #pragma unroll
            for (int k = 0; k < KNN; k++) {
                if (cd < bd[k]) {
                    float td = bd[k]; int ti = bi[k];
                    bd[k] = cd; bi[k] = ci; cd = td; ci = ti;
                }
            }
        }
        #pragma unroll
        for (int k = 0; k < KNN; k++) g_nbr[(b*NB + t)*KNN + k] = bi[k];
    }
}

// ---------------- kernel 2: feat MLP + A/C GEMM (unchanged) ----------------
__global__ __launch_bounds__(256, 2) void k_feat(
    const float* __restrict__ state_inp, const float* __restrict__ tar,
    const float* __restrict__ W_in1, const float* __restrict__ b_in1,
    const float* __restrict__ W_in2, const float* __restrict__ b_in2,
    const float* __restrict__ b_m1)
{
    __shared__ float s_in4[32][4];
    __shared__ float s_t[128][P];
    __shared__ float s_f[192][P];
    const int tid = threadIdx.x;
    const int row0 = blockIdx.x * 32;

    if (tid < 128) {
        int r = tid >> 2, q = tid & 3;
        int row = row0 + r;
        int b = row / NB, n = row - b*NB;
        float v = (q < 2) ? state_inp[b*60 + 2*n + q] : tanha(tar[row*2 + (q-2)]);
        s_in4[r][q] = v;
    }
    for (int idx = tid; idx < 32*EMB; idx += 256) {
        int r = idx & 31, e = idx >> 5;
        int n = (row0 + r) % NB;
        s_f[128 + e][r] = g_cf[n*EMB + e];
    }
    __syncthreads();

    {
        const int c  = tid & 127;
        const int rh = tid >> 7;
        float w0 = W_in1[c], w1 = W_in1[128+c], w2 = W_in1[256+c], w3 = W_in1[384+c];
        float bb = b_in1[c];
        #pragma unroll
        for (int m = 0; m < 16; m++) {
            int r = rh*16 + m;
            float4 in = *reinterpret_cast<const float4*>(&s_in4[r][0]);
            s_t[c][r] = tanha(bb + w0*in.x + w1*in.y + w2*in.z + w3*in.w);
        }
    }
    __syncthreads();

    const int g  = tid >> 6;
    const int rb = g*8;

    {
        const int c2 = tid & 63;
        u64 acc[4][2];
        #pragma unroll
        for (int q = 0; q < 4; q++) { acc[q][0] = 0ull; acc[q][1] = 0ull; }
        #pragma unroll 4
        for (int k = 0; k < 128; k++) {
            float2 w = *reinterpret_cast<const float2*>(&W_in2[k*128 + 2*c2]);
            u64 w0 = pk(w.x), w1 = pk(w.y);
            #pragma unroll
            for (int q = 0; q < 4; q++) {
                u64 tv = *reinterpret_cast<const u64*>(&s_t[k][rb + 2*q]);
                acc[q][0] = fma2(tv, w0, acc[q][0]);
                acc[q][1] = fma2(tv, w1, acc[q][1]);
            }
        }
        float2 bb = *reinterpret_cast<const float2*>(&b_in2[2*c2]);
        #pragma unroll
        for (int q = 0; q < 4; q++) {
            float2 a0 = up(acc[q][0]), a1 = up(acc[q][1]);
            s_f[2*c2  ][rb + 2*q]   = tanha(a0.x + bb.x);
            s_f[2*c2  ][rb + 2*q+1] = tanha(a0.y + bb.x);
            s_f[2*c2+1][rb + 2*q]   = tanha(a1.x + bb.y);
            s_f[2*c2+1][rb + 2*q+1] = tanha(a1.y + bb.y);
        }
    }
    __syncthreads();

    {
        const int c4 = tid & 63;
        u64 acc[4][4];
        #pragma unroll
        for (int q = 0; q < 4; q++)
            #pragma unroll
            for (int n = 0; n < 4; n++) acc[q][n] = 0ull;
        #pragma unroll 2
        for (int k = 0; k < 192; k++) {
            float4 w = *reinterpret_cast<const float4*>(&g_Wcomb[k*256 + 4*c4]);
            u64 w0 = pk(w.x), w1 = pk(w.y), w2 = pk(w.z), w3 = pk(w.w);
            #pragma unroll
            for (int q = 0; q < 4; q++) {
                u64 fv = *reinterpret_cast<const u64*>(&s_f[k][rb + 2*q]);
                acc[q][0] = fma2(fv, w0, acc[q][0]);
                acc[q][1] = fma2(fv, w1, acc[q][1]);
                acc[q][2] = fma2(fv, w2, acc[q][2]);
                acc[q][3] = fma2(fv, w3, acc[q][3]);
            }
        }
        if (c4 < 32) {
            float4 bb = *reinterpret_cast<const float4*>(&b_m1[4*c4]);
            #pragma unroll
            for (int q = 0; q < 4; q++) {
                float2 a0 = up(acc[q][0]), a1 = up(acc[q][1]), a2 = up(acc[q][2]), a3 = up(acc[q][3]);
                *reinterpret_cast<float4*>(&g_C[(row0+rb+2*q  )*128 + 4*c4]) =
                    make_float4(a0.x+bb.x, a1.x+bb.y, a2.x+bb.z, a3.x+bb.w);
                *reinterpret_cast<float4*>(&g_C[(row0+rb+2*q+1)*128 + 4*c4]) =
                    make_float4(a0.y+bb.x, a1.y+bb.y, a2.y+bb.z, a3.y+bb.w);
            }
        } else {
            int ca = 4*c4 - 128;
            #pragma unroll
            for (int q = 0; q < 4; q++) {
                float2 a0 = up(acc[q][0]), a1 = up(acc[q][1]), a2 = up(acc[q][2]), a3 = up(acc[q][3]);
                *reinterpret_cast<float4*>(&g_A[(row0+rb+2*q  )*128 + ca]) =
                    make_float4(a0.x, a1.x, a2.x, a3.x);
                *reinterpret_cast<float4*>(&g_A[(row0+rb+2*q+1)*128 + ca]) =
                    make_float4(a0.y, a1.y, a2.y, a3.y);
            }
        }
    }
}

// ---------------- kernel 3: edge msg via mma.sync tf32 (64 rows/block) ----------------
// dynamic smem (floats):
#define OF_M   0                   // s_m: 64 x PK (tf32 operand / y)
#define OF_B   (64*PK)             // s_B: 128 x PB (tf32 weight)
#define OF_NB  (OF_B + 128*PB)
#define SMEM_MSG_BYTES ((OF_NB + RMSG*KNN) * 4)

__global__ __launch_bounds__(256, 2) void k_msg(
    const float* __restrict__ tar,
    const float* __restrict__ W_m2, const float* __restrict__ b_m2,
    const float* __restrict__ W_a1, const float* __restrict__ b_a1,
    const float* __restrict__ W_a2, const float* __restrict__ b_a2,
    float* __restrict__ out)
{
    extern __shared__ float smem[];
    unsigned* s_m  = (unsigned*)(smem + OF_M);
    unsigned* s_B  = (unsigned*)(smem + OF_B);
    int*      s_nb = (int*)(smem + OF_NB);

    const int tid  = threadIdx.x;
    const int wid  = tid >> 5;
    const int lane = tid & 31;
    const int rg   = wid >> 2;          // 0..1 : rows rg*32..+31
    const int cg   = wid & 3;           // 0..3 : cols cg*32..+31
    const int gid  = lane >> 2;         // 0..7
    const int tig  = lane & 3;          // 0..3
    const int row0 = blockIdx.x * RMSG;

    // stage W_m2 (tf32) into s_B
    for (int i = tid; i < 128*32; i += 256) {
        int k = i >> 5, c4 = (i & 31) * 4;
        float4 w = *reinterpret_cast<const float4*>(&W_m2[k*128 + c4]);
        uint4 v = make_uint4(tf32r(w.x), tf32r(w.y), tf32r(w.z), tf32r(w.w));
        *reinterpret_cast<uint4*>(&s_B[k*PB + c4]) = v;
    }
    for (int idx = tid; idx < RMSG*KNN; idx += 256) {
        int r = idx / KNN;
        int b = (row0 + r) / NB;
        s_nb[idx] = b*NB + g_nbr[row0*KNN + idx];
    }
    __syncthreads();

    float vmax[2][4][4];
    #pragma unroll
    for (int mi = 0; mi < 2; mi++)
        #pragma unroll
        for (int ni = 0; ni < 4; ni++)
            #pragma unroll
            for (int q = 0; q < 4; q++) vmax[mi][ni][q] = -1e30f;

    for (int k = 0; k < KNN; k++) {
        // build operand: s_m[r][j] = tf32(ptanh(C + A_nbr))  -- fma-pipe tanh, no MUFU
        #pragma unroll
        for (int it = 0; it < 8; it++) {
            int p = tid + 256*it;               // 2048 float4 slots
            int r = p >> 5, j = (p & 31) * 4;
            float4 a = *reinterpret_cast<const float4*>(&g_A[s_nb[r*KNN + k]*128 + j]);
            float4 c = *reinterpret_cast<const float4*>(&g_C[(row0 + r)*128 + j]);
            uint4 v = make_uint4(tf32r(ptanh(c.x + a.x)), tf32r(ptanh(c.y + a.y)),
                                 tf32r(ptanh(c.z + a.z)), tf32r(ptanh(c.w + a.w)));
            *reinterpret_cast<uint4*>(&s_m[r*PK + j]) = v;
        }
        __syncthreads();

        float acc[2][4][4];
        #pragma unroll
        for (int mi = 0; mi < 2; mi++)
            #pragma unroll
            for (int ni = 0; ni < 4; ni++)
                #pragma unroll
                for (int q = 0; q < 4; q++) acc[mi][ni][q] = 0.f;

        #pragma unroll
        for (int ks = 0; ks < 16; ks++) {
            int k0 = ks * 8;
            unsigned a[2][4];
            #pragma unroll
            for (int mi = 0; mi < 2; mi++) {
                int r = rg*32 + mi*16 + gid;
                a[mi][0] = s_m[r*PK + k0 + tig];
                a[mi][1] = s_m[(r+8)*PK + k0 + tig];
                a[mi][2] = s_m[r*PK + k0 + 4 + tig];
                a[mi][3] = s_m[(r+8)*PK + k0 + 4 + tig];
            }
            #pragma unroll
            for (int ni = 0; ni < 4; ni++) {
                int col = cg*32 + ni*8 + gid;
                unsigned b0 = s_B[(k0 + tig)*PB + col];
                unsigned b1 = s_B[(k0 + 4 + tig)*PB + col];
                MMA_TF32(acc[0][ni][0], acc[0][ni][1], acc[0][ni][2], acc[0][ni][3],
                         a[0][0], a[0][1], a[0][2], a[0][3], b0, b1);
                MMA_TF32(acc[1][ni][0], acc[1][ni][1], acc[1][ni][2], acc[1][ni][3],
                         a[1][0], a[1][1], a[1][2], a[1][3], b0, b1);
            }
        }
        #pragma unroll
        for (int mi = 0; mi < 2; mi++)
            #pragma unroll
            for (int ni = 0; ni < 4; ni++)
                #pragma unroll
                for (int q = 0; q < 4; q++)
                    vmax[mi][ni][q] = fmaxf(vmax[mi][ni][q], acc[mi][ni][q]);
        __syncthreads();
    }

    // x = tanh(vmax + b_m2) -> s_m (tf32, [row][col] == [row][k] for next GEMM)
    #pragma unroll
    for (int mi = 0; mi < 2; mi++)
        #pragma unroll
        for (int ni = 0; ni < 4; ni++)
            #pragma unroll
            for (int q = 0; q < 4; q++) {
                int row = rg*32 + mi*16 + gid + ((q >= 2) ? 8 : 0);
                int col = cg*32 + ni*8 + 2*tig + (q & 1);
                float xv = tanha(vmax[mi][ni][q] + b_m2[col]);
                s_m[row*PK + col] = tf32r(xv);
            }
    // stage W_a1 into s_B
    for (int i = tid; i < 128*32; i += 256) {
        int k2 = i >> 5, c4 = (i & 31) * 4;
        float4 w = *reinterpret_cast<const float4*>(&W_a1[k2*128 + c4]);
        uint4 v = make_uint4(tf32r(w.x), tf32r(w.y), tf32r(w.z), tf32r(w.w));
        *reinterpret_cast<uint4*>(&s_B[k2*PB + c4]) = v;
    }
    __syncthreads();

    // y-GEMM
    float acc[2][4][4];
    #pragma unroll
    for (int mi = 0; mi < 2; mi++)
        #pragma unroll
        for (int ni = 0; ni < 4; ni++)
            #pragma unroll
            for (int q = 0; q < 4; q++) acc[mi][ni][q] = 0.f;
    #pragma unroll
    for (int ks = 0; ks < 16; ks++) {
        int k0 = ks * 8;
        unsigned a[2][4];
        #pragma unroll
        for (int mi = 0; mi < 2; mi++) {
            int r = rg*32 + mi*16 + gid;
            a[mi][0] = s_m[r*PK + k0 + tig];
            a[mi][1] = s_m[(r+8)*PK + k0 + tig];
            a[mi][2] = s_m[r*PK + k0 + 4 + tig];
            a[mi][3] = s_m[(r+8)*PK + k0 + 4 + tig];
        }
        #pragma unroll
        for (int ni = 0; ni < 4; ni++) {
            int col = cg*32 + ni*8 + gid;
            unsigned b0 = s_B[(k0 + tig)*PB + col];
            unsigned b1 = s_B[(k0 + 4 + tig)*PB + col];
            MMA_TF32(acc[0][ni][0], acc[0][ni][1], acc[0][ni][2], acc[0][ni][3],
                     a[0][0], a[0][1], a[0][2], a[0][3], b0, b1);
            MMA_TF32(acc[1][ni][0], acc[1][ni][1], acc[1][ni][2], acc[1][ni][3],
                     a[1][0], a[1][1], a[1][2], a[1][3], b0, b1);
        }
    }
    __syncthreads();     // all x reads done before overwriting s_m with y

    // y = tanh(acc + b_a1) -> s_y (float, [row][col])
    float* s_y = (float*)s_m;
    #pragma unroll
    for (int mi = 0; mi < 2; mi++)
        #pragma unroll
        for (int ni = 0; ni < 4; ni++)
            #pragma unroll
            for (int q = 0; q < 4; q++) {
                int row = rg*32 + mi*16 + gid + ((q >= 2) ? 8 : 0);
                int col = cg*32 + ni*8 + 2*tig + (q & 1);
                s_y[row*PK + col] = tanha(acc[mi][ni][q] + b_a1[col]);
            }
    __syncthreads();

    // final 128 -> 4, exact squashing (64 rows x 4 outs = 256 threads)
    {
        int r = tid >> 2, o = tid & 3;
        float s = b_a2[o];
        #pragma unroll 4
        for (int kk = 0; kk < 128; kk++) s += s_y[r*PK + kk] * W_a2[kk*4 + o];
        int row = row0 + r;
        int b = row / NB, n = row - b*NB;
        if (o < 2) {
            float tv = tar[row*2 + o];
            out[b*60 + 2*n + o] = 0.3f*tanhf(s) + 0.3f*tanhf(tv);
        } else {
            float t = tanhf(s);
            out[BSZ*60 + b*60 + 2*n + (o-2)] = expf(3.5f*t - 1.5f);
        }
    }
}

// ---------------- launch ----------------
extern "C" void kernel_launch(void* const* d_in, const int* in_sizes, int n_in,
                              void* d_out, int out_size)
{
    const float* state_inp = (const float*)d_in[0];
    const float* tar       = (const float*)d_in[1];
    const float* W_in1     = (const float*)d_in[2];
    const float* b_in1     = (const float*)d_in[3];
    const float* W_in2     = (const float*)d_in[4];
    const float* b_in2     = (const float*)d_in[5];
    const float* emb_tab   = (const float*)d_in[6];
    const float* W_emb     = (const float*)d_in[7];
    const float* b_emb     = (const float*)d_in[8];
    const float* W_m1      = (const float*)d_in[9];
    const float* b_m1      = (const float*)d_in[10];
    const float* W_m2      = (const float*)d_in[11];
    const float* b_m2      = (const float*)d_in[12];
    const float* W_a1      = (const float*)d_in[13];
    const float* b_a1      = (const float*)d_in[14];
    const float* W_a2      = (const float*)d_in[15];
    const float* b_a2      = (const float*)d_in[16];
    float* out = (float*)d_out;

    cudaFuncSetAttribute(k_msg, cudaFuncAttributeMaxDynamicSharedMemorySize, SMEM_MSG_BYTES);

    k_setup<<<64, 256>>>(emb_tab, W_emb, b_emb, W_m1);
    k_knn<<<BSZ, 32>>>(state_inp);
    k_feat<<<NROWS/32, 256>>>(state_inp, tar, W_in1, b_in1, W_in2, b_in2, b_m1);
    k_msg<<<NROWS/RMSG, 256, SMEM_MSG_BYTES>>>(tar, W_m2, b_m2, W_a1, b_a1, W_a2, b_a2, out);
}

// round 10
// speedup vs baseline: 1.3248x; 1.3248x over previous
#include <cuda_runtime.h>
#include <math.h>

#define BSZ   1024
#define NB    30
#define KNN   10
#define HID   128
#define EMB   64
#define NROWS (BSZ*NB)
#define RMSG  64          // rows per k_msg block
#define PK    132         // operand pitch: bank-conflict-free A frags
#define PB    136         // weight pitch : bank-conflict-free B frags

typedef unsigned long long u64;

__device__ __forceinline__ float tanha(float x) {
    float y; asm("tanh.approx.f32 %0, %1;" : "=f"(y) : "f"(x)); return y;
}
__device__ __forceinline__ unsigned tf32r(float x) {
    unsigned r; asm("cvt.rna.tf32.f32 %0, %1;" : "=r"(r) : "f"(x)); return r;
}

#define MMA_TF32(d0,d1,d2,d3,a0,a1,a2,a3,b0,b1) \
    asm volatile("mma.sync.aligned.m16n8k8.row.col.f32.tf32.tf32.f32 " \
        "{%0,%1,%2,%3},{%4,%5,%6,%7},{%8,%9},{%0,%1,%2,%3};" \
        : "+f"(d0),"+f"(d1),"+f"(d2),"+f"(d3) \
        : "r"(a0),"r"(a1),"r"(a2),"r"(a3),"r"(b0),"r"(b1))

// ---------------- device scratch ----------------
__device__ float g_cf[NB*EMB];
__device__ float g_Wcomb[192*256];
__device__ int   g_nbr[NROWS*KNN];
__device__ float g_A[NROWS*HID];
__device__ float g_C[NROWS*HID];

// ---------------- kernel 0: tiny precompute ----------------
__global__ void k_setup(const float* __restrict__ emb_tab,
                        const float* __restrict__ W_emb,
                        const float* __restrict__ b_emb,
                        const float* __restrict__ W_m1)
{
    int tid = blockIdx.x * blockDim.x + threadIdx.x;
    int stride = gridDim.x * blockDim.x;
    for (int idx = tid; idx < NB*EMB; idx += stride) {
        int n = idx / EMB, e = idx - n*EMB;
        int cat = n / (NB/3);
        float s = b_emb[e];
        for (int k = 0; k < EMB; k++)
            s += tanhf(emb_tab[cat*EMB + k]) * W_emb[k*EMB + e];
        g_cf[idx] = tanhf(s);
    }
    for (int idx = tid; idx < 192*256; idx += stride) {
        int k = idx >> 8, c = idx & 255;
        float v;
        if (c < 128) v = W_m1[k*128 + c] - W_m1[(192+k)*128 + c];
        else         v = W_m1[(192+k)*128 + (c-128)];
        g_Wcomb[idx] = v;
    }
}

// ---------------- kernel 1: per-batch KNN ----------------
__global__ void k_knn(const float* __restrict__ state_inp)
{
    __shared__ float px[NB], py[NB];
    int b = blockIdx.x, t = threadIdx.x;
    if (t < NB) { px[t] = state_inp[b*60 + 2*t]; py[t] = state_inp[b*60 + 2*t + 1]; }
    __syncthreads();
    if (t < NB) {
        float bd[KNN]; int bi[KNN];
        #pragma unroll
        for (int k = 0; k < KNN; k++) { bd[k] = 1e30f; bi[k] = 0; }
        float xi = px[t], yi = py[t];
        for (int j = 0; j < NB; j++) {
            if (j == t) continue;
            float dx = px[j] - xi, dy = py[j] - yi;
            float cd = dx*dx + dy*dy;
            int ci = j;
            #pragma unroll
            for (int k = 0; k < KNN; k++) {
                if (cd < bd[k]) {
                    float td = bd[k]; int ti = bi[k];
                    bd[k] = cd; bi[k] = ci; cd = td; ci = ti;
                }
            }
        }
        #pragma unroll
        for (int k = 0; k < KNN; k++) g_nbr[(b*NB + t)*KNN + k] = bi[k];
    }
}

// ---------------- kernel 2: feat MLP + A/C GEMM via mma tf32 (32 rows/block) ----------------
// dynamic smem (floats):
#define FK_PF  196                       // s_f pitch (192-k operand)
#define FK_OT  0                         // s_t: 32 x PK (tf32 stage-2 operand; reused as fp32 staging)
#define FK_OF  (32*PK)                   // s_f: 32 x FK_PF (tf32 stage-3 operand: [f | cf])
#define FK_OB  (FK_OF + 32*FK_PF)        // s_B: 64 x PB (weight chunk)
#define FK_SMEM ((FK_OB + 64*PB) * 4)

__global__ __launch_bounds__(256, 2) void k_feat(
    const float* __restrict__ state_inp, const float* __restrict__ tar,
    const float* __restrict__ W_in1, const float* __restrict__ b_in1,
    const float* __restrict__ W_in2, const float* __restrict__ b_in2,
    const float* __restrict__ b_m1)
{
    extern __shared__ float smem[];
    unsigned* s_t = (unsigned*)(smem + FK_OT);
    unsigned* s_f = (unsigned*)(smem + FK_OF);
    unsigned* s_B = (unsigned*)(smem + FK_OB);
    __shared__ float s_in4[32][4];

    const int tid  = threadIdx.x;
    const int wid  = tid >> 5;          // cg = wid (8 col groups of 16)
    const int lane = tid & 31;
    const int gid  = lane >> 2;
    const int tig  = lane & 3;
    const int row0 = blockIdx.x * 32;

    // inputs + cf
    if (tid < 128) {
        int r = tid >> 2, q = tid & 3;
        int row = row0 + r;
        int b = row / NB, n = row - b*NB;
        float v = (q < 2) ? state_inp[b*60 + 2*n + q] : tanha(tar[row*2 + (q-2)]);
        s_in4[r][q] = v;
    }
    for (int idx = tid; idx < 32*EMB; idx += 256) {
        int r = idx & 31, e = idx >> 5;
        int n = (row0 + r) % NB;
        s_f[r*FK_PF + 128 + e] = tf32r(g_cf[n*EMB + e]);
    }
    __syncthreads();

    // stage 1: t = tanh(inp4 @ W_in1 + b_in1) -> s_t tf32 [row][k]
    {
        const int c  = tid & 127;
        const int rh = tid >> 7;
        float w0 = W_in1[c], w1 = W_in1[128+c], w2 = W_in1[256+c], w3 = W_in1[384+c];
        float bb = b_in1[c];
        #pragma unroll
        for (int m = 0; m < 16; m++) {
            int r = rh*16 + m;
            float4 in = *reinterpret_cast<const float4*>(&s_in4[r][0]);
            s_t[r*PK + c] = tf32r(tanha(bb + w0*in.x + w1*in.y + w2*in.z + w3*in.w));
        }
    }

    // stage 2: h = t @ W_in2 (mma, 2 K-chunks of 64); f = tanh(h + b_in2) -> s_f
    {
        float acc[2][2][4];
        #pragma unroll
        for (int mi = 0; mi < 2; mi++)
            #pragma unroll
            for (int ni = 0; ni < 2; ni++)
                #pragma unroll
                for (int q = 0; q < 4; q++) acc[mi][ni][q] = 0.f;

        for (int ch = 0; ch < 2; ch++) {
            __syncthreads();
            for (int i = tid; i < 64*32; i += 256) {
                int kr = i >> 5, c4 = (i & 31) * 4;
                float4 w = *reinterpret_cast<const float4*>(&W_in2[(ch*64 + kr)*128 + c4]);
                uint4 v = make_uint4(tf32r(w.x), tf32r(w.y), tf32r(w.z), tf32r(w.w));
                *reinterpret_cast<uint4*>(&s_B[kr*PB + c4]) = v;
            }
            __syncthreads();
            #pragma unroll
            for (int ks = 0; ks < 8; ks++) {
                int kg = ch*64 + ks*8, k0 = ks*8;
                unsigned a[2][4];
                #pragma unroll
                for (int mi = 0; mi < 2; mi++) {
                    int r = mi*16 + gid;
                    a[mi][0] = s_t[r*PK + kg + tig];
                    a[mi][1] = s_t[(r+8)*PK + kg + tig];
                    a[mi][2] = s_t[r*PK + kg + 4 + tig];
                    a[mi][3] = s_t[(r+8)*PK + kg + 4 + tig];
                }
                #pragma unroll
                for (int ni = 0; ni < 2; ni++) {
                    int col = wid*16 + ni*8 + gid;
                    unsigned b0 = s_B[(k0 + tig)*PB + col];
                    unsigned b1 = s_B[(k0 + 4 + tig)*PB + col];
                    MMA_TF32(acc[0][ni][0], acc[0][ni][1], acc[0][ni][2], acc[0][ni][3],
                             a[0][0], a[0][1], a[0][2], a[0][3], b0, b1);
                    MMA_TF32(acc[1][ni][0], acc[1][ni][1], acc[1][ni][2], acc[1][ni][3],
                             a[1][0], a[1][1], a[1][2], a[1][3], b0, b1);
                }
            }
        }
        #pragma unroll
        for (int mi = 0; mi < 2; mi++)
            #pragma unroll
            for (int ni = 0; ni < 2; ni++)
                #pragma unroll
                for (int q = 0; q < 4; q++) {
                    int row = mi*16 + gid + ((q >= 2) ? 8 : 0);
                    int col = wid*16 + ni*8 + 2*tig + (q & 1);
                    s_f[row*FK_PF + col] = tf32r(tanha(acc[mi][ni][q] + b_in2[col]));
                }
    }

    // stage 3: [C|A] = f192 @ Wcomb (mma, 2 halves x 3 K-chunks of 64)
    float* s_stg = (float*)s_t;   // fp32 staging, pitch PK
    for (int half = 0; half < 2; half++) {
        float acc[2][2][4];
        #pragma unroll
        for (int mi = 0; mi < 2; mi++)
            #pragma unroll
            for (int ni = 0; ni < 2; ni++)
                #pragma unroll
                for (int q = 0; q < 4; q++) acc[mi][ni][q] = 0.f;

        for (int ch = 0; ch < 3; ch++) {
            __syncthreads();
            for (int i = tid; i < 64*32; i += 256) {
                int kr = i >> 5, c4 = (i & 31) * 4;
                float4 w = *reinterpret_cast<const float4*>(&g_Wcomb[(ch*64 + kr)*256 + half*128 + c4]);
                uint4 v = make_uint4(tf32r(w.x), tf32r(w.y), tf32r(w.z), tf32r(w.w));
                *reinterpret_cast<uint4*>(&s_B[kr*PB + c4]) = v;
            }
            __syncthreads();
            #pragma unroll
            for (int ks = 0; ks < 8; ks++) {
                int kg = ch*64 + ks*8, k0 = ks*8;
                unsigned a[2][4];
                #pragma unroll
                for (int mi = 0; mi < 2; mi++) {
                    int r = mi*16 + gid;
                    a[mi][0] = s_f[r*FK_PF + kg + tig];
                    a[mi][1] = s_f[(r+8)*FK_PF + kg + tig];
                    a[mi][2] = s_f[r*FK_PF + kg + 4 + tig];
                    a[mi][3] = s_f[(r+8)*FK_PF + kg + 4 + tig];
                }
                #pragma unroll
                for (int ni = 0; ni < 2; ni++) {
                    int col = wid*16 + ni*8 + gid;
                    unsigned b0 = s_B[(k0 + tig)*PB + col];
                    unsigned b1 = s_B[(k0 + 4 + tig)*PB + col];
                    MMA_TF32(acc[0][ni][0], acc[0][ni][1], acc[0][ni][2], acc[0][ni][3],
                             a[0][0], a[0][1], a[0][2], a[0][3], b0, b1);
                    MMA_TF32(acc[1][ni][0], acc[1][ni][1], acc[1][ni][2], acc[1][ni][3],
                             a[1][0], a[1][1], a[1][2], a[1][3], b0, b1);
                }
            }
        }
        // bias + stage to smem, then coalesced store
        #pragma unroll
        for (int mi = 0; mi < 2; mi++)
            #pragma unroll
            for (int ni = 0; ni < 2; ni++)
                #pragma unroll
                for (int q = 0; q < 4; q++) {
                    int row = mi*16 + gid + ((q >= 2) ? 8 : 0);
                    int col = wid*16 + ni*8 + 2*tig + (q & 1);
                    float v = acc[mi][ni][q] + (half == 0 ? b_m1[col] : 0.0f);
                    s_stg[row*PK + col] = v;
                }
        __syncthreads();
        float* dst = (half == 0) ? g_C : g_A;
        for (int i = tid; i < 32*32; i += 256) {
            int r = i >> 5, c4 = (i & 31) * 4;
            float4 v = *reinterpret_cast<const float4*>(&s_stg[r*PK + c4]);
            *reinterpret_cast<float4*>(&dst[(row0 + r)*128 + c4]) = v;
        }
    }
}

// ---------------- kernel 3: edge msg via mma.sync tf32 (64 rows/block) ----------------
// dynamic smem (floats):
#define OF_M   0                   // s_m: 64 x PK (tf32 operand / y)
#define OF_B   (64*PK)             // s_B: 128 x PB (tf32 weight)
#define OF_NB  (OF_B + 128*PB)
#define SMEM_MSG_BYTES ((OF_NB + RMSG*KNN) * 4)

__global__ __launch_bounds__(256, 2) void k_msg(
    const float* __restrict__ tar,
    const float* __restrict__ W_m2, const float* __restrict__ b_m2,
    const float* __restrict__ W_a1, const float* __restrict__ b_a1,
    const float* __restrict__ W_a2, const float* __restrict__ b_a2,
    float* __restrict__ out)
{
    extern __shared__ float smem[];
    unsigned* s_m  = (unsigned*)(smem + OF_M);
    unsigned* s_B  = (unsigned*)(smem + OF_B);
    int*      s_nb = (int*)(smem + OF_NB);

    const int tid  = threadIdx.x;
    const int wid  = tid >> 5;
    const int lane = tid & 31;
    const int rg   = wid >> 2;
    const int cg   = wid & 3;
    const int gid  = lane >> 2;
    const int tig  = lane & 3;
    const int row0 = blockIdx.x * RMSG;

    for (int i = tid; i < 128*32; i += 256) {
        int k = i >> 5, c4 = (i & 31) * 4;
        float4 w = *reinterpret_cast<const float4*>(&W_m2[k*128 + c4]);
        uint4 v = make_uint4(tf32r(w.x), tf32r(w.y), tf32r(w.z), tf32r(w.w));
        *reinterpret_cast<uint4*>(&s_B[k*PB + c4]) = v;
    }
    for (int idx = tid; idx < RMSG*KNN; idx += 256) {
        int r = idx / KNN;
        int b = (row0 + r) / NB;
        s_nb[idx] = b*NB + g_nbr[row0*KNN + idx];
    }
    __syncthreads();

    float vmax[2][4][4];
    #pragma unroll
    for (int mi = 0; mi < 2; mi++)
        #pragma unroll
        for (int ni = 0; ni < 4; ni++)
            #pragma unroll
            for (int q = 0; q < 4; q++) vmax[mi][ni][q] = -1e30f;

    for (int k = 0; k < KNN; k++) {
        #pragma unroll
        for (int it = 0; it < 8; it++) {
            int p = tid + 256*it;
            int r = p >> 5, j = (p & 31) * 4;
            float4 a = *reinterpret_cast<const float4*>(&g_A[s_nb[r*KNN + k]*128 + j]);
            float4 c = *reinterpret_cast<const float4*>(&g_C[(row0 + r)*128 + j]);
            uint4 v = make_uint4(tf32r(tanha(c.x + a.x)), tf32r(tanha(c.y + a.y)),
                                 tf32r(tanha(c.z + a.z)), tf32r(tanha(c.w + a.w)));
            *reinterpret_cast<uint4*>(&s_m[r*PK + j]) = v;
        }
        __syncthreads();

        float acc[2][4][4];
        #pragma unroll
        for (int mi = 0; mi < 2; mi++)
            #pragma unroll
            for (int ni = 0; ni < 4; ni++)
                #pragma unroll
                for (int q = 0; q < 4; q++) acc[mi][ni][q] = 0.f;

        #pragma unroll
        for (int ks = 0; ks < 16; ks++) {
            int k0 = ks * 8;
            unsigned a[2][4];
            #pragma unroll
            for (int mi = 0; mi < 2; mi++) {
                int r = rg*32 + mi*16 + gid;
                a[mi][0] = s_m[r*PK + k0 + tig];
                a[mi][1] = s_m[(r+8)*PK + k0 + tig];
                a[mi][2] = s_m[r*PK + k0 + 4 + tig];
                a[mi][3] = s_m[(r+8)*PK + k0 + 4 + tig];
            }
            #pragma unroll
            for (int ni = 0; ni < 4; ni++) {
                int col = cg*32 + ni*8 + gid;
                unsigned b0 = s_B[(k0 + tig)*PB + col];
                unsigned b1 = s_B[(k0 + 4 + tig)*PB + col];
                MMA_TF32(acc[0][ni][0], acc[0][ni][1], acc[0][ni][2], acc[0][ni][3],
                         a[0][0], a[0][1], a[0][2], a[0][3], b0, b1);
                MMA_TF32(acc[1][ni][0], acc[1][ni][1], acc[1][ni][2], acc[1][ni][3],
                         a[1][0], a[1][1], a[1][2], a[1][3], b0, b1);
            }
        }
        #pragma unroll
        for (int mi = 0; mi < 2; mi++)
            #pragma unroll
            for (int ni = 0; ni < 4; ni++)
                #pragma unroll
                for (int q = 0; q < 4; q++)
                    vmax[mi][ni][q] = fmaxf(vmax[mi][ni][q], acc[mi][ni][q]);
        __syncthreads();
    }

    // x = tanh(vmax + b_m2) -> s_m (tf32)
    #pragma unroll
    for (int mi = 0; mi < 2; mi++)
        #pragma unroll
        for (int ni = 0; ni < 4; ni++)
            #pragma unroll
            for (int q = 0; q < 4; q++) {
                int row = rg*32 + mi*16 + gid + ((q >= 2) ? 8 : 0);
                int col = cg*32 + ni*8 + 2*tig + (q & 1);
                float xv = tanha(vmax[mi][ni][q] + b_m2[col]);
                s_m[row*PK + col] = tf32r(xv);
            }
    for (int i = tid; i < 128*32; i += 256) {
        int k2 = i >> 5, c4 = (i & 31) * 4;
        float4 w = *reinterpret_cast<const float4*>(&W_a1[k2*128 + c4]);
        uint4 v = make_uint4(tf32r(w.x), tf32r(w.y), tf32r(w.z), tf32r(w.w));
        *reinterpret_cast<uint4*>(&s_B[k2*PB + c4]) = v;
    }
    __syncthreads();

    // y-GEMM
    float acc[2][4][4];
    #pragma unroll
    for (int mi = 0; mi < 2; mi++)
        #pragma unroll
        for (int ni = 0; ni < 4; ni++)
            #pragma unroll
            for (int q = 0; q < 4; q++) acc[mi][ni][q] = 0.f;
    #pragma unroll
    for (int ks = 0; ks < 16; ks++) {
        int k0 = ks * 8;
        unsigned a[2][4];
        #pragma unroll
        for (int mi = 0; mi < 2; mi++) {
            int r = rg*32 + mi*16 + gid;
            a[mi][0] = s_m[r*PK + k0 + tig];
            a[mi][1] = s_m[(r+8)*PK + k0 + tig];
            a[mi][2] = s_m[r*PK + k0 + 4 + tig];
            a[mi][3] = s_m[(r+8)*PK + k0 + 4 + tig];
        }
        #pragma unroll
        for (int ni = 0; ni < 4; ni++) {
            int col = cg*32 + ni*8 + gid;
            unsigned b0 = s_B[(k0 + tig)*PB + col];
            unsigned b1 = s_B[(k0 + 4 + tig)*PB + col];
            MMA_TF32(acc[0][ni][0], acc[0][ni][1], acc[0][ni][2], acc[0][ni][3],
                     a[0][0], a[0][1], a[0][2], a[0][3], b0, b1);
            MMA_TF32(acc[1][ni][0], acc[1][ni][1], acc[1][ni][2], acc[1][ni][3],
                     a[1][0], a[1][1], a[1][2], a[1][3], b0, b1);
        }
    }
    __syncthreads();

    float* s_y = (float*)s_m;
    #pragma unroll
    for (int mi = 0; mi < 2; mi++)
        #pragma unroll
        for (int ni = 0; ni < 4; ni++)
            #pragma unroll
            for (int q = 0; q < 4; q++) {
                int row = rg*32 + mi*16 + gid + ((q >= 2) ? 8 : 0);
                int col = cg*32 + ni*8 + 2*tig + (q & 1);
                s_y[row*PK + col] = tanha(acc[mi][ni][q] + b_a1[col]);
            }
    __syncthreads();

    {
        int r = tid >> 2, o = tid & 3;
        float s = b_a2[o];
        #pragma unroll 4
        for (int kk = 0; kk < 128; kk++) s += s_y[r*PK + kk] * W_a2[kk*4 + o];
        int row = row0 + r;
        int b = row / NB, n = row - b*NB;
        if (o < 2) {
            float tv = tar[row*2 + o];
            out[b*60 + 2*n + o] = 0.3f*tanhf(s) + 0.3f*tanhf(tv);
        } else {
            float t = tanhf(s);
            out[BSZ*60 + b*60 + 2*n + (o-2)] = expf(3.5f*t - 1.5f);
        }
    }
}

// ---------------- launch ----------------
extern "C" void kernel_launch(void* const* d_in, const int* in_sizes, int n_in,
                              void* d_out, int out_size)
{
    const float* state_inp = (const float*)d_in[0];
    const float* tar       = (const float*)d_in[1];
    const float* W_in1     = (const float*)d_in[2];
    const float* b_in1     = (const float*)d_in[3];
    const float* W_in2     = (const float*)d_in[4];
    const float* b_in2     = (const float*)d_in[5];
    const float* emb_tab   = (const float*)d_in[6];
    const float* W_emb     = (const float*)d_in[7];
    const float* b_emb     = (const float*)d_in[8];
    const float* W_m1      = (const float*)d_in[9];
    const float* b_m1      = (const float*)d_in[10];
    const float* W_m2      = (const float*)d_in[11];
    const float* b_m2      = (const float*)d_in[12];
    const float* W_a1      = (const float*)d_in[13];
    const float* b_a1      = (const float*)d_in[14];
    const float* W_a2      = (const float*)d_in[15];
    const float* b_a2      = (const float*)d_in[16];
    float* out = (float*)d_out;

    cudaFuncSetAttribute(k_feat, cudaFuncAttributeMaxDynamicSharedMemorySize, FK_SMEM);
    cudaFuncSetAttribute(k_msg,  cudaFuncAttributeMaxDynamicSharedMemorySize, SMEM_MSG_BYTES);

    k_setup<<<64, 256>>>(emb_tab, W_emb, b_emb, W_m1);
    k_knn<<<BSZ, 32>>>(state_inp);
    k_feat<<<NROWS/32, 256, FK_SMEM>>>(state_inp, tar, W_in1, b_in1, W_in2, b_in2, b_m1);
    k_msg<<<NROWS/RMSG, 256, SMEM_MSG_BYTES>>>(tar, W_m2, b_m2, W_a1, b_a1, W_a2, b_a2, out);
}